// round 17
// baseline (speedup 1.0000x reference)
#include <cuda_runtime.h>
#include <math.h>

// ============================================================================
// Per-observable light-cone simulation: <Z_w> depends on exactly 5 qubits
// -> 32 amps -> one warp per observable, 1 amplitude per lane.
// Per warp: 5 L0 rotations (analytic product init), 4 CZ0 pairs (fused sign),
// 3 L1 shuffle gates, 2 CZ1 pairs (fused sign), 1 L2 gate, warp reduction.
// This revision packs each 2x2 unitary as two float4s so a lane's (A,B)
// coefficients are ONE LDS.128 selected by its own bit, and prefetches all
// 9 smem reads immediately after __syncwarp (single LDS latency window).
// ============================================================================

__device__ __forceinline__ float2 cmul(float2 a, float2 b) {
    return make_float2(a.x * b.x - a.y * b.y, a.x * b.y + a.y * b.x);
}

// Apply a 2x2 gate: g = (A.x,A.y,B.x,B.y) already selected for this lane.
__device__ __forceinline__ void apply_gate(float2& amp, unsigned M, float4 g)
{
    float wr = __shfl_xor_sync(0xFFFFFFFFu, amp.x, M);
    float wi = __shfl_xor_sync(0xFFFFFFFFu, amp.y, M);
    float ar = amp.x, ai = amp.y;
    amp.x = g.x * ar - g.y * ai + g.z * wr - g.w * wi;
    amp.y = g.x * ai + g.y * ar + g.z * wi + g.w * wr;
}

__global__ void __launch_bounds__(256, 1) qve_kernel(const float* __restrict__ inputs,
                                                     const float* __restrict__ yw,
                                                     const float* __restrict__ zw,
                                                     float* __restrict__ out)
{
    // [warp][gate][bit]: bit=0 -> (u00,u01), bit=1 -> (u11,u10)
    __shared__ float4 sU[8][9][2];

    const unsigned tid  = threadIdx.x;
    const unsigned lane = tid & 31u;
    const int      w    = (int)(tid >> 5);    // warp id = observable index

    // ------------------------------------------------------------------
    // Setup: lanes 0..8 each build one fused rotation (RZ)*RY*RX.
    //   j in [0,5): layer 0, gw = cone[w][j]        (with RZ)
    //   j in [5,8): layer 1, gw = l1 wires           (with RZ)
    //   j == 8:     layer 2, gw = w                  (z=0 -> RZ identity)
    // ------------------------------------------------------------------
    if (lane < 9) {
        const int j = (int)lane;
        int gw, layer;
        bool withRZ;
        if (j < 5) {
            layer = 0; withRZ = true;
            gw = (w >= 2) ? (w - 2 + j)
               : (w == 0) ? ((j < 3) ? j : 14 + j)      // {0,1,2,17,18}
                          : ((j < 4) ? j : 18);          // {0,1,2,3,18}
        } else if (j < 8) {
            const int k = j - 5;
            layer = 1; withRZ = true;
            gw = (w >= 2) ? (w - 1 + k)
               : (w == 1) ? k
                          : ((k < 2) ? k : 18);          // {0,1,18}
        } else {
            layer = 2; withRZ = false; gw = w;
        }

        const float TWO_PI = 6.28318530717958647692f;
        const float PI_F   = 3.14159265358979323846f;
        float x = inputs[gw];
        float asc = (x + 1.5f) * (TWO_PI / 3.0f);
        asc = fminf(fmaxf(asc, 0.0f), TWO_PI);
        float adir = (x >= 0.5f) ? PI_F : 0.0f;
        float a = (gw >= 17) ? adir : asc;

        float sx, cx; __sincosf(0.5f * a, &sx, &cx);
        float y = yw[layer * 19 + gw];
        float sy, cy; __sincosf(0.5f * y, &sy, &cy);
        // M = RY*RX
        float2 m00 = make_float2( cy * cx,  sy * sx);
        float2 m01 = make_float2(-sy * cx, -cy * sx);
        float2 m10 = make_float2( sy * cx, -cy * sx);
        float2 m11 = make_float2( cy * cx, -sy * sx);
        // RZ fold; z = 0 when dropped (identity)
        float z = withRZ ? zw[layer * 19 + gw] : 0.0f;
        float sz, cz; __sincosf(0.5f * z, &sz, &cz);
        float2 e0 = make_float2(cz, -sz), e1 = make_float2(cz, sz);
        float2 v0 = cmul(e0, m00), v1 = cmul(e0, m01);
        float2 v2 = cmul(e1, m10), v3 = cmul(e1, m11);
        sU[w][j][0] = make_float4(v0.x, v0.y, v1.x, v1.y);   // bit=0: (u00,u01)
        sU[w][j][1] = make_float4(v3.x, v3.y, v2.x, v2.y);   // bit=1: (u11,u10)
    }
    __syncwarp();

    // ---- L1 gate positions + measured-wire bit (uniform selects) ----
    int p0, p1, p2;
    if (w >= 2)      { p0 = 1; p1 = 2; p2 = 3; }
    else if (w == 1) { p0 = 0; p1 = 1; p2 = 2; }
    else             { p0 = 0; p1 = 1; p2 = 4; }
    const int pw = (w < 2) ? w : 2;

    // ---- prefetch ALL smem: 5 init factors + 4 gate matrices ----
    float4 f0 = sU[w][0][ lane       & 1u];
    float4 f1 = sU[w][1][(lane >> 1) & 1u];
    float4 f2 = sU[w][2][(lane >> 2) & 1u];
    float4 f3 = sU[w][3][(lane >> 3) & 1u];
    float4 f4 = sU[w][4][(lane >> 4) & 1u];
    float4 g5 = sU[w][5][(lane >> p0) & 1u];
    float4 g6 = sU[w][6][(lane >> p1) & 1u];
    float4 g7 = sU[w][7][(lane >> p2) & 1u];
    float4 g8 = sU[w][8][(lane >> pw) & 1u];

    // ---- init: L0 product state (column 0). Packed f: bit=0 -> u00 = .xy,
    //      bit=1 -> u10 = .zw (since [1]=(u11,u10)). Tree multiply, depth 3.
    float2 c0 = ( lane       & 1u) ? make_float2(f0.z, f0.w) : make_float2(f0.x, f0.y);
    float2 c1 = ((lane >> 1) & 1u) ? make_float2(f1.z, f1.w) : make_float2(f1.x, f1.y);
    float2 c2 = ((lane >> 2) & 1u) ? make_float2(f2.z, f2.w) : make_float2(f2.x, f2.y);
    float2 c3 = ((lane >> 3) & 1u) ? make_float2(f3.z, f3.w) : make_float2(f3.x, f3.y);
    float2 c4 = ((lane >> 4) & 1u) ? make_float2(f4.z, f4.w) : make_float2(f4.x, f4.y);
    float2 amp = cmul(cmul(cmul(c0, c1), cmul(c2, c3)), c4);

    // ---- CZ0 sign (4 kept pairs) folded right after init ----
    {
        unsigned q = lane & (lane >> 1);     // bit k = bit_k & bit_{k+1}
        unsigned par;
        if (w >= 2)      par = __popc(q & 0xFu);                       // (0,1)(1,2)(2,3)(3,4)
        else if (w == 1) par = __popc(q & 0x7u)                        // (0,1)(1,2)(2,3)
                             + ((lane & (lane >> 4)) & 1u);            // (0,4)
        else             par = __popc(q & 0x3u)                        // (0,1)(1,2)
                             + ((lane & (lane >> 4)) & 1u)             // (0,4)
                             + (((lane >> 3) & (lane >> 4)) & 1u);     // (3,4)
        if (par & 1u) { amp.x = -amp.x; amp.y = -amp.y; }
    }

    // ---- L1 rotations (3 shuffle gates) ----
    apply_gate(amp, 1u << p0, g5);
    apply_gate(amp, 1u << p1, g6);
    apply_gate(amp, 1u << p2, g7);

    // ---- CZ1 sign (2 kept pairs) ----
    {
        unsigned q = lane & (lane >> 1);
        unsigned par;
        if (w >= 2)      par = __popc(q & 0x6u);                       // (1,2)(2,3)
        else if (w == 1) par = __popc(q & 0x3u);                       // (0,1)(1,2)
        else             par = (q & 1u)                                // (0,1)
                             + ((lane & (lane >> 4)) & 1u);            // (0,4)
        if (par & 1u) { amp.x = -amp.x; amp.y = -amp.y; }
    }

    // ---- L2 rotation on the measured wire ----
    apply_gate(amp, 1u << pw, g8);

    // ---- <Z_w> = sum over lanes of (+-)|amp|^2 ----
    float p = amp.x * amp.x + amp.y * amp.y;
    float zv = ((lane >> pw) & 1u) ? -p : p;
    #pragma unroll
    for (int o = 16; o > 0; o >>= 1)
        zv += __shfl_xor_sync(0xFFFFFFFFu, zv, o);

    if (lane == 0) out[w] = zv;
}

extern "C" void kernel_launch(void* const* d_in, const int* in_sizes, int n_in,
                              void* d_out, int out_size)
{
    (void)in_sizes; (void)n_in; (void)out_size;
    const float* inputs = (const float*)d_in[0];
    const float* yw     = (const float*)d_in[1];
    const float* zw     = (const float*)d_in[2];
    float* out = (float*)d_out;

    qve_kernel<<<1, 256>>>(inputs, yw, zw, out);
}